// round 4
// baseline (speedup 1.0000x reference)
#include <cuda_runtime.h>
#include <cstdint>

// Problem constants (fixed by the dataset; guarded by runtime sizes in launch).
#define NMAX 100000
#define HF   64      // hidden features
#define CF   40      // classes

// Scratch (device globals; no allocation allowed). Referenced ONLY from device
// code — their addresses never appear as host-side kernel arguments.
__device__ __align__(16) float g_A[(size_t)NMAX * HF];   // linear outputs
__device__ __align__(16) float g_B[(size_t)NMAX * HF];   // aggregation buffer
__device__ __align__(16) float g_dinv[NMAX];             // degree -> rsqrt in place

// ---------------------------------------------------------------- utilities
__global__ void k_fill_deg(int N) {
    int i = blockIdx.x * blockDim.x + threadIdx.x;
    if (i < N) g_dinv[i] = 1.0f;  // self loop contributes 1
}

// NOTE: edge_index is int32 (JAX default x64-disabled downcasts the reference's
// "int64" request). Reading it as int64 was the cause of rounds 1-3 failing.
__global__ void k_deg_accum(const int* __restrict__ ei, int E) {
    int e = blockIdx.x * blockDim.x + threadIdx.x;
    if (e < E) {
        int d = ei[E + e];
        atomicAdd(&g_dinv[d], 1.0f);
    }
}

__global__ void k_dinv(int N) {
    int i = blockIdx.x * blockDim.x + threadIdx.x;
    if (i < N) g_dinv[i] = rsqrtf(g_dinv[i]);  // deg >= 1 always (self loops)
}

// ------------------------------------------------------------------- GEMMs
// g_A[N,64] = SRC[N,K] @ W[K,64].  SRC is the external pointer X if SRC_EXT,
// otherwise the internal g_B. One row per thread, W staged in shared.
template <int K, bool SRC_EXT>
__global__ void k_gemm(const float* __restrict__ X, const float* __restrict__ W,
                       int N) {
    __shared__ float Ws[K * HF];
    for (int i = threadIdx.x; i < K * HF; i += blockDim.x) Ws[i] = W[i];
    __syncthreads();

    int row = blockIdx.x * blockDim.x + threadIdx.x;
    if (row >= N) return;

    const float* src = SRC_EXT ? X : (const float*)g_B;

    float acc[HF];
#pragma unroll
    for (int n = 0; n < HF; n++) acc[n] = 0.0f;

    const float4* xr = reinterpret_cast<const float4*>(src + (size_t)row * K);
#pragma unroll
    for (int k4 = 0; k4 < K / 4; k4++) {
        float4 xv = xr[k4];
        const float* w0 = &Ws[(k4 * 4 + 0) * HF];
        const float* w1 = &Ws[(k4 * 4 + 1) * HF];
        const float* w2 = &Ws[(k4 * 4 + 2) * HF];
        const float* w3 = &Ws[(k4 * 4 + 3) * HF];
#pragma unroll
        for (int n = 0; n < HF; n++) {
            acc[n] += xv.x * w0[n];
            acc[n] += xv.y * w1[n];
            acc[n] += xv.z * w2[n];
            acc[n] += xv.w * w3[n];
        }
    }

    float4* yr = reinterpret_cast<float4*>(g_A + (size_t)row * HF);
#pragma unroll
    for (int n = 0; n < HF / 4; n++) {
        float4 v;
        v.x = acc[n * 4 + 0]; v.y = acc[n * 4 + 1];
        v.z = acc[n * 4 + 2]; v.w = acc[n * 4 + 3];
        yr[n] = v;
    }
}

// -------------------------------------------------- aggregation init (self loop)
// B[i,:] = A[i,:] * dinv[i]^2    (also serves as the zero-init of the agg buffer)
__global__ void k_init_agg(int N) {
    int idx = blockIdx.x * blockDim.x + threadIdx.x;  // over N * (HF/4) float4s
    int total = N * (HF / 4);
    if (idx >= total) return;
    int i = idx / (HF / 4);
    float di = g_dinv[i];
    float s = di * di;
    float4 v = reinterpret_cast<const float4*>(g_A)[idx];
    v.x *= s; v.y *= s; v.z *= s; v.w *= s;
    reinterpret_cast<float4*>(g_B)[idx] = v;
}

// ------------------------------------------------------------ edge scatter-add
// B[dst,:] += A[src,:] * dinv[src] * dinv[dst]
// One edge per half-warp; each lane handles one float4 (4 scalar REDG adds).
__global__ void k_scatter(const int* __restrict__ ei, int E) {
    int gt = blockIdx.x * blockDim.x + threadIdx.x;
    int warp = gt >> 5;
    int lane = gt & 31;
    int e = warp * 2 + (lane >> 4);
    if (e >= E) return;
    int sub = lane & 15;

    int s = __ldg(&ei[e]);
    int d = __ldg(&ei[E + e]);
    float nrm = g_dinv[s] * g_dinv[d];

    float4 v = reinterpret_cast<const float4*>(g_A + (size_t)s * HF)[sub];

    float* p = g_B + (size_t)d * HF + sub * 4;
    atomicAdd(p + 0, v.x * nrm);
    atomicAdd(p + 1, v.y * nrm);
    atomicAdd(p + 2, v.z * nrm);
    atomicAdd(p + 3, v.w * nrm);
}

// ---------------------------------------------------------- bias + relu inplace
__global__ void k_bias_relu(const float* __restrict__ b, int N) {
    int idx = blockIdx.x * blockDim.x + threadIdx.x;  // N * (HF/4) float4s
    int total = N * (HF / 4);
    if (idx >= total) return;
    int j = (idx & (HF / 4 - 1)) * 4;
    float4 v = reinterpret_cast<const float4*>(g_B)[idx];
    v.x = fmaxf(v.x + b[j + 0], 0.0f);
    v.y = fmaxf(v.y + b[j + 1], 0.0f);
    v.z = fmaxf(v.z + b[j + 2], 0.0f);
    v.w = fmaxf(v.w + b[j + 3], 0.0f);
    reinterpret_cast<float4*>(g_B)[idx] = v;
}

// ------------------------------------------- classifier: out = relu(B + b2) @ Wc + bc
__global__ void k_final(const float* __restrict__ b2, const float* __restrict__ Wc,
                        const float* __restrict__ bc, float* __restrict__ out, int N) {
    __shared__ float Ws[HF * CF];
    __shared__ float bs[HF];
    __shared__ float bcs[CF];
    for (int i = threadIdx.x; i < HF * CF; i += blockDim.x) Ws[i] = Wc[i];
    if (threadIdx.x < HF) bs[threadIdx.x] = b2[threadIdx.x];
    if (threadIdx.x < CF) bcs[threadIdx.x] = bc[threadIdx.x];
    __syncthreads();

    int row = blockIdx.x * blockDim.x + threadIdx.x;
    if (row >= N) return;

    float acc[CF];
#pragma unroll
    for (int n = 0; n < CF; n++) acc[n] = bcs[n];

    const float4* br = reinterpret_cast<const float4*>(g_B + (size_t)row * HF);
#pragma unroll
    for (int k4 = 0; k4 < HF / 4; k4++) {
        float4 v = br[k4];
        int k = k4 * 4;
        float a0 = fmaxf(v.x + bs[k + 0], 0.0f);
        float a1 = fmaxf(v.y + bs[k + 1], 0.0f);
        float a2 = fmaxf(v.z + bs[k + 2], 0.0f);
        float a3 = fmaxf(v.w + bs[k + 3], 0.0f);
#pragma unroll
        for (int n = 0; n < CF; n++) {
            acc[n] += a0 * Ws[(k + 0) * CF + n];
            acc[n] += a1 * Ws[(k + 1) * CF + n];
            acc[n] += a2 * Ws[(k + 2) * CF + n];
            acc[n] += a3 * Ws[(k + 3) * CF + n];
        }
    }

    float4* orow = reinterpret_cast<float4*>(out + (size_t)row * CF);
#pragma unroll
    for (int n = 0; n < CF / 4; n++) {
        float4 v;
        v.x = acc[n * 4 + 0]; v.y = acc[n * 4 + 1];
        v.z = acc[n * 4 + 2]; v.w = acc[n * 4 + 3];
        orow[n] = v;
    }
}

// ------------------------------------------------------------------ launcher
extern "C" void kernel_launch(void* const* d_in, const int* in_sizes, int n_in,
                              void* d_out, int out_size) {
    const float* x  = (const float*)d_in[0];
    const int*   ei = (const int*)d_in[1];     // int32! (JAX x64-disabled)
    const float* W1 = (const float*)d_in[2];
    const float* b1 = (const float*)d_in[3];
    const float* W2 = (const float*)d_in[4];
    const float* b2 = (const float*)d_in[5];
    const float* Wc = (const float*)d_in[6];
    const float* bc = (const float*)d_in[7];
    float*       out = (float*)d_out;

    const int Hdim = in_sizes[3];             // 64
    const int Fin  = in_sizes[2] / Hdim;      // 128
    const int N    = in_sizes[0] / Fin;       // 100000
    const int E    = in_sizes[1] / 2;         // 1000000
    (void)Hdim; (void)n_in; (void)out_size;

    const int TPB = 256;
    int nBlk  = (N + TPB - 1) / TPB;
    int eBlk  = (E + TPB - 1) / TPB;
    int v4    = N * (HF / 4);
    int v4Blk = (v4 + TPB - 1) / TPB;
    // scatter: one edge per half-warp -> E/2 warps -> E*16 threads
    long long scatThreads = (long long)((E + 1) / 2) * 32;
    int scatBlk = (int)((scatThreads + TPB - 1) / TPB);

    // degrees -> dinv
    k_fill_deg<<<nBlk, TPB>>>(N);
    k_deg_accum<<<eBlk, TPB>>>(ei, E);
    k_dinv<<<nBlk, TPB>>>(N);

    // layer 1: A = x @ W1 ; B = normalize-aggregate(A) ; B = relu(B + b1)
    k_gemm<128, true><<<nBlk, TPB>>>(x, W1, N);
    k_init_agg<<<v4Blk, TPB>>>(N);
    k_scatter<<<scatBlk, TPB>>>(ei, E);
    k_bias_relu<<<v4Blk, TPB>>>(b1, N);

    // layer 2: A = B @ W2 ; B = normalize-aggregate(A)
    k_gemm<64, false><<<nBlk, TPB>>>(nullptr, W2, N);
    k_init_agg<<<v4Blk, TPB>>>(N);
    k_scatter<<<scatBlk, TPB>>>(ei, E);

    // classifier (fuses relu(B + b2))
    k_final<<<nBlk, TPB>>>(b2, Wc, bc, out, N);
}

// round 5
// speedup vs baseline: 1.2442x; 1.2442x over previous
#include <cuda_runtime.h>
#include <cstdint>

#define NMAX 100000
#define HF   64      // hidden features
#define CF   40      // classes

// Device-only scratch. Never passed from host.
__device__ __align__(16) float g_A [(size_t)NMAX * HF];  // linear outputs (scatter source)
__device__ __align__(16) float g_B1[(size_t)NMAX * HF];  // layer-1 aggregation buffer
__device__ __align__(16) float g_B2[(size_t)NMAX * HF];  // layer-2 aggregation buffer
__device__ __align__(16) float g_dinv[NMAX];

// ---------------------------------------------------------------- degrees
__global__ void k_fill_deg(int N) {
    int i = blockIdx.x * blockDim.x + threadIdx.x;
    if (i < N) g_dinv[i] = 1.0f;  // self loop
}
__global__ void k_deg_accum(const int* __restrict__ ei, int E) {
    int e = blockIdx.x * blockDim.x + threadIdx.x;
    if (e < E) atomicAdd(&g_dinv[ei[E + e]], 1.0f);
}
__global__ void k_dinv(int N) {
    int i = blockIdx.x * blockDim.x + threadIdx.x;
    if (i < N) g_dinv[i] = rsqrtf(g_dinv[i]);
}

// ------------------------------------------------------------------- GEMM
// A[row] = in[row] @ W ; Bout[row] = A[row] * dinv[row]^2   (fused self-loop init)
// in = X (external) if SRC_EXT else relu(g_B1 + bias) elementwise (fused layer-1 epilogue).
// 2 threads per row, 32 output columns each -> acc[32], better occupancy.
template <int K, bool SRC_EXT, int OUTBUF>   // OUTBUF: 1 -> g_B1, 2 -> g_B2
__global__ void __launch_bounds__(256)
k_gemm(const float* __restrict__ X, const float* __restrict__ W,
       const float* __restrict__ bias, int N) {
    __shared__ float Ws[K * HF];
    __shared__ float bs[HF];
    for (int i = threadIdx.x; i < K * HF; i += blockDim.x) Ws[i] = W[i];
    if (!SRC_EXT && threadIdx.x < K) bs[threadIdx.x] = bias[threadIdx.x];
    __syncthreads();

    int row  = blockIdx.x * 128 + (threadIdx.x >> 1);
    int half = threadIdx.x & 1;                 // which 32-column slice
    if (row >= N) return;

    const float* src = SRC_EXT ? X : (const float*)g_B1;

    float acc[32];
#pragma unroll
    for (int n = 0; n < 32; n++) acc[n] = 0.0f;

    const float4* xr = reinterpret_cast<const float4*>(src + (size_t)row * K);
    const float* wbase = &Ws[half * 32];
#pragma unroll
    for (int k4 = 0; k4 < K / 4; k4++) {
        float4 xv = xr[k4];
        if (!SRC_EXT) {   // fused relu(prev_agg + b1) on load
            int k = k4 * 4;
            xv.x = fmaxf(xv.x + bs[k + 0], 0.0f);
            xv.y = fmaxf(xv.y + bs[k + 1], 0.0f);
            xv.z = fmaxf(xv.z + bs[k + 2], 0.0f);
            xv.w = fmaxf(xv.w + bs[k + 3], 0.0f);
        }
        const float* w0 = wbase + (k4 * 4 + 0) * HF;
        const float* w1 = wbase + (k4 * 4 + 1) * HF;
        const float* w2 = wbase + (k4 * 4 + 2) * HF;
        const float* w3 = wbase + (k4 * 4 + 3) * HF;
#pragma unroll
        for (int n = 0; n < 32; n++) {
            acc[n] += xv.x * w0[n];
            acc[n] += xv.y * w1[n];
            acc[n] += xv.z * w2[n];
            acc[n] += xv.w * w3[n];
        }
    }

    float di = g_dinv[row];
    float s  = di * di;
    float* bout = (OUTBUF == 1) ? g_B1 : g_B2;
    float4* ya = reinterpret_cast<float4*>(g_A  + (size_t)row * HF + half * 32);
    float4* yb = reinterpret_cast<float4*>(bout + (size_t)row * HF + half * 32);
#pragma unroll
    for (int n = 0; n < 8; n++) {
        float4 v;
        v.x = acc[n * 4 + 0]; v.y = acc[n * 4 + 1];
        v.z = acc[n * 4 + 2]; v.w = acc[n * 4 + 3];
        ya[n] = v;
        float4 vb;
        vb.x = v.x * s; vb.y = v.y * s; vb.z = v.z * s; vb.w = v.w * s;
        yb[n] = vb;
    }
}

// ------------------------------------------------------------ edge scatter-add
// Bout[dst,:] += A[src,:] * dinv[src] * dinv[dst]
// One edge per half-warp; each lane issues ONE red.global.add.v4.f32.
template <int OUTBUF>
__global__ void k_scatter(const int* __restrict__ ei, int E) {
    int gt   = blockIdx.x * blockDim.x + threadIdx.x;
    int warp = gt >> 5;
    int lane = gt & 31;
    int e = warp * 2 + (lane >> 4);
    if (e >= E) return;
    int sub = lane & 15;

    int s = __ldg(&ei[e]);
    int d = __ldg(&ei[E + e]);
    float nrm = g_dinv[s] * g_dinv[d];

    float4 v = reinterpret_cast<const float4*>(g_A + (size_t)s * HF)[sub];
    v.x *= nrm; v.y *= nrm; v.z *= nrm; v.w *= nrm;

    float* bout = (OUTBUF == 1) ? g_B1 : g_B2;
    float* p = bout + (size_t)d * HF + sub * 4;
    asm volatile("red.global.add.v4.f32 [%0], {%1, %2, %3, %4};"
                 :: "l"(p), "f"(v.x), "f"(v.y), "f"(v.z), "f"(v.w)
                 : "memory");
}

// ------------------------------------------- classifier: out = relu(B2 + b2) @ Wc + bc
__global__ void __launch_bounds__(256)
k_final(const float* __restrict__ b2, const float* __restrict__ Wc,
        const float* __restrict__ bc, float* __restrict__ out, int N) {
    __shared__ float Ws[HF * CF];
    __shared__ float bs[HF];
    __shared__ float bcs[CF];
    for (int i = threadIdx.x; i < HF * CF; i += blockDim.x) Ws[i] = Wc[i];
    if (threadIdx.x < HF) bs[threadIdx.x] = b2[threadIdx.x];
    if (threadIdx.x < CF) bcs[threadIdx.x] = bc[threadIdx.x];
    __syncthreads();

    int row = blockIdx.x * blockDim.x + threadIdx.x;
    if (row >= N) return;

    float acc[CF];
#pragma unroll
    for (int n = 0; n < CF; n++) acc[n] = bcs[n];

    const float4* br = reinterpret_cast<const float4*>(g_B2 + (size_t)row * HF);
#pragma unroll
    for (int k4 = 0; k4 < HF / 4; k4++) {
        float4 v = br[k4];
        int k = k4 * 4;
        float a0 = fmaxf(v.x + bs[k + 0], 0.0f);
        float a1 = fmaxf(v.y + bs[k + 1], 0.0f);
        float a2 = fmaxf(v.z + bs[k + 2], 0.0f);
        float a3 = fmaxf(v.w + bs[k + 3], 0.0f);
#pragma unroll
        for (int n = 0; n < CF; n++) {
            acc[n] += a0 * Ws[(k + 0) * CF + n];
            acc[n] += a1 * Ws[(k + 1) * CF + n];
            acc[n] += a2 * Ws[(k + 2) * CF + n];
            acc[n] += a3 * Ws[(k + 3) * CF + n];
        }
    }

    float4* orow = reinterpret_cast<float4*>(out + (size_t)row * CF);
#pragma unroll
    for (int n = 0; n < CF / 4; n++) {
        float4 v;
        v.x = acc[n * 4 + 0]; v.y = acc[n * 4 + 1];
        v.z = acc[n * 4 + 2]; v.w = acc[n * 4 + 3];
        orow[n] = v;
    }
}

// ------------------------------------------------------------------ launcher
extern "C" void kernel_launch(void* const* d_in, const int* in_sizes, int n_in,
                              void* d_out, int out_size) {
    const float* x  = (const float*)d_in[0];
    const int*   ei = (const int*)d_in[1];     // int32 (JAX x64-disabled)
    const float* W1 = (const float*)d_in[2];
    const float* b1 = (const float*)d_in[3];
    const float* W2 = (const float*)d_in[4];
    const float* b2 = (const float*)d_in[5];
    const float* Wc = (const float*)d_in[6];
    const float* bc = (const float*)d_in[7];
    float*       out = (float*)d_out;

    const int Hdim = in_sizes[3];             // 64
    const int Fin  = in_sizes[2] / Hdim;      // 128
    const int N    = in_sizes[0] / Fin;       // 100000
    const int E    = in_sizes[1] / 2;         // 1000000
    (void)Hdim; (void)n_in; (void)out_size;

    const int TPB = 256;
    int nBlk  = (N + TPB - 1) / TPB;
    int eBlk  = (E + TPB - 1) / TPB;
    int gBlk  = (N + 127) / 128;              // gemm: 2 threads/row
    long long scatThreads = (long long)((E + 1) / 2) * 32;
    int scatBlk = (int)((scatThreads + TPB - 1) / TPB);

    // degrees -> dinv
    k_fill_deg<<<nBlk, TPB>>>(N);
    k_deg_accum<<<eBlk, TPB>>>(ei, E);
    k_dinv<<<nBlk, TPB>>>(N);

    // layer 1: A = x@W1 ; B1 = A*dinv^2 (fused) ; B1 += scatter(A)
    k_gemm<128, true, 1><<<gBlk, TPB>>>(x, W1, nullptr, N);
    k_scatter<1><<<scatBlk, TPB>>>(ei, E);

    // layer 2: A = relu(B1+b1)@W2 (fused load) ; B2 = A*dinv^2 ; B2 += scatter(A)
    k_gemm<64, false, 2><<<gBlk, TPB>>>(nullptr, W2, b1, N);
    k_scatter<2><<<scatBlk, TPB>>>(ei, E);

    // classifier (fuses relu(B2 + b2))
    k_final<<<nBlk, TPB>>>(b2, Wc, bc, out, N);
}

// round 6
// speedup vs baseline: 1.8655x; 1.4993x over previous
#include <cuda_runtime.h>
#include <cstdint>

#define NMAX 100000
#define HF   64      // hidden features
#define CF   40      // classes

// Device-only scratch. Never passed from host.
__device__ __align__(16) float g_A [(size_t)NMAX * HF];  // linear outputs (scatter source)
__device__ __align__(16) float g_B1[(size_t)NMAX * HF];  // layer-1 aggregation buffer
__device__ __align__(16) float g_B2[(size_t)NMAX * HF];  // layer-2 aggregation buffer
__device__ __align__(16) float g_dinv[NMAX];

// ---------------------------------------------------------------- degrees
__global__ void k_fill_deg(int N) {
    int i = blockIdx.x * blockDim.x + threadIdx.x;
    if (i < N) g_dinv[i] = 1.0f;  // self loop
}
__global__ void k_deg_accum(const int* __restrict__ ei, int E) {
    int e = blockIdx.x * blockDim.x + threadIdx.x;
    if (e < E) atomicAdd(&g_dinv[ei[E + e]], 1.0f);
}
__global__ void k_dinv(int N) {
    int i = blockIdx.x * blockDim.x + threadIdx.x;
    if (i < N) g_dinv[i] = rsqrtf(g_dinv[i]);
}

// ------------------------------------------------------- tiled GEMM (2D reg-blocked)
// A[row] = in[row] @ W[K,64]; Bout[row] = A[row]*dinv[row]^2 (fused self-loop init).
// in = X if SRC_EXT else relu(g_B1 + bias) applied during tile staging.
// Block: 128 rows x 64 cols, BK=16, 256 threads, 8x4 register tile per thread.
#define BM   128
#define BK   16
#define XSTR 132   // padded row stride for Xs (kills STS bank conflicts)

template <int K, bool SRC_EXT, int OUTBUF>   // OUTBUF: 1 -> g_B1, 2 -> g_B2
__global__ void __launch_bounds__(256)
k_gemm(const float* __restrict__ X, const float* __restrict__ W,
       const float* __restrict__ bias, int N) {
    __shared__ float Ws[K * HF];        // full W resident (<=32KB)
    __shared__ float Xs[BK * XSTR];     // staged X tile, transposed [k][row]
    __shared__ float bs[K];             // bias for fused relu (layer 2 only)

    const int tid = threadIdx.x;
    {   // stage W once (float4)
        const float4* Wv = reinterpret_cast<const float4*>(W);
        float4* Wsv = reinterpret_cast<float4*>(Ws);
        for (int i = tid; i < K * HF / 4; i += 256) Wsv[i] = Wv[i];
        if (!SRC_EXT && tid < K) bs[tid] = bias[tid];
    }

    const int bm = blockIdx.x * BM;
    const int tc = tid & 15;            // col group: cols tc*4 .. tc*4+3
    const int tr = tid >> 4;            // row group: rows tr*8 .. tr*8+7

    const float* src = SRC_EXT ? X : (const float*)g_B1;

    float acc[8][4];
#pragma unroll
    for (int i = 0; i < 8; i++)
#pragma unroll
        for (int j = 0; j < 4; j++) acc[i][j] = 0.0f;

    __syncthreads();

    for (int k0 = 0; k0 < K; k0 += BK) {
        // stage Xs[kk][row] = relu-opt(src[bm+row][k0+kk]); 512 float4 loads
#pragma unroll
        for (int i = tid; i < BM * BK / 4; i += 256) {
            int row = i >> 2;           // 0..127
            int kq  = i & 3;            // float4 index within the 16-k chunk
            int r   = bm + row;
            float4 v = make_float4(0.f, 0.f, 0.f, 0.f);
            if (r < N) {
                v = *reinterpret_cast<const float4*>(src + (size_t)r * K + k0 + kq * 4);
                if (!SRC_EXT) {
                    int kb = k0 + kq * 4;
                    v.x = fmaxf(v.x + bs[kb + 0], 0.0f);
                    v.y = fmaxf(v.y + bs[kb + 1], 0.0f);
                    v.z = fmaxf(v.z + bs[kb + 2], 0.0f);
                    v.w = fmaxf(v.w + bs[kb + 3], 0.0f);
                }
            }
            Xs[(kq * 4 + 0) * XSTR + row] = v.x;
            Xs[(kq * 4 + 1) * XSTR + row] = v.y;
            Xs[(kq * 4 + 2) * XSTR + row] = v.z;
            Xs[(kq * 4 + 3) * XSTR + row] = v.w;
        }
        __syncthreads();

#pragma unroll
        for (int kk = 0; kk < BK; kk++) {
            float4 xa = *reinterpret_cast<const float4*>(&Xs[kk * XSTR + tr * 8 + 0]);
            float4 xb = *reinterpret_cast<const float4*>(&Xs[kk * XSTR + tr * 8 + 4]);
            float4 wv = *reinterpret_cast<const float4*>(&Ws[(k0 + kk) * HF + tc * 4]);
            float xr[8] = {xa.x, xa.y, xa.z, xa.w, xb.x, xb.y, xb.z, xb.w};
#pragma unroll
            for (int i = 0; i < 8; i++) {
                acc[i][0] += xr[i] * wv.x;
                acc[i][1] += xr[i] * wv.y;
                acc[i][2] += xr[i] * wv.z;
                acc[i][3] += xr[i] * wv.w;
            }
        }
        __syncthreads();
    }

    // epilogue: write A and Bout = A * dinv^2
    float* bout = (OUTBUF == 1) ? g_B1 : g_B2;
#pragma unroll
    for (int i = 0; i < 8; i++) {
        int r = bm + tr * 8 + i;
        if (r >= N) break;
        float di = g_dinv[r];
        float s  = di * di;
        float4 v = make_float4(acc[i][0], acc[i][1], acc[i][2], acc[i][3]);
        *reinterpret_cast<float4*>(g_A + (size_t)r * HF + tc * 4) = v;
        float4 vb = make_float4(v.x * s, v.y * s, v.z * s, v.w * s);
        *reinterpret_cast<float4*>(bout + (size_t)r * HF + tc * 4) = vb;
    }
}

// ------------------------------------------------------------ edge scatter-add
// Bout[dst,:] += A[src,:] * dinv[src] * dinv[dst]
// One edge per half-warp; each lane issues ONE red.global.add.v4.f32.
template <int OUTBUF>
__global__ void k_scatter(const int* __restrict__ ei, int E) {
    int gt   = blockIdx.x * blockDim.x + threadIdx.x;
    int warp = gt >> 5;
    int lane = gt & 31;
    int e = warp * 2 + (lane >> 4);
    if (e >= E) return;
    int sub = lane & 15;

    int s = __ldg(&ei[e]);
    int d = __ldg(&ei[E + e]);
    float nrm = g_dinv[s] * g_dinv[d];

    float4 v = reinterpret_cast<const float4*>(g_A + (size_t)s * HF)[sub];
    v.x *= nrm; v.y *= nrm; v.z *= nrm; v.w *= nrm;

    float* bout = (OUTBUF == 1) ? g_B1 : g_B2;
    float* p = bout + (size_t)d * HF + sub * 4;
    asm volatile("red.global.add.v4.f32 [%0], {%1, %2, %3, %4};"
                 :: "l"(p), "f"(v.x), "f"(v.y), "f"(v.z), "f"(v.w)
                 : "memory");
}

// ------------------------------------------- classifier: out = relu(B2 + b2) @ Wc + bc
__global__ void __launch_bounds__(256)
k_final(const float* __restrict__ b2, const float* __restrict__ Wc,
        const float* __restrict__ bc, float* __restrict__ out, int N) {
    __shared__ float Ws[HF * CF];
    __shared__ float bs[HF];
    __shared__ float bcs[CF];
    for (int i = threadIdx.x; i < HF * CF; i += blockDim.x) Ws[i] = Wc[i];
    if (threadIdx.x < HF) bs[threadIdx.x] = b2[threadIdx.x];
    if (threadIdx.x < CF) bcs[threadIdx.x] = bc[threadIdx.x];
    __syncthreads();

    int row = blockIdx.x * blockDim.x + threadIdx.x;
    if (row >= N) return;

    float acc[CF];
#pragma unroll
    for (int n = 0; n < CF; n++) acc[n] = bcs[n];

    const float4* br = reinterpret_cast<const float4*>(g_B2 + (size_t)row * HF);
#pragma unroll
    for (int k4 = 0; k4 < HF / 4; k4++) {
        float4 v = br[k4];
        int k = k4 * 4;
        float a0 = fmaxf(v.x + bs[k + 0], 0.0f);
        float a1 = fmaxf(v.y + bs[k + 1], 0.0f);
        float a2 = fmaxf(v.z + bs[k + 2], 0.0f);
        float a3 = fmaxf(v.w + bs[k + 3], 0.0f);
#pragma unroll
        for (int n = 0; n < CF; n++) {
            acc[n] += a0 * Ws[(k + 0) * CF + n];
            acc[n] += a1 * Ws[(k + 1) * CF + n];
            acc[n] += a2 * Ws[(k + 2) * CF + n];
            acc[n] += a3 * Ws[(k + 3) * CF + n];
        }
    }

    float4* orow = reinterpret_cast<float4*>(out + (size_t)row * CF);
#pragma unroll
    for (int n = 0; n < CF / 4; n++) {
        float4 v;
        v.x = acc[n * 4 + 0]; v.y = acc[n * 4 + 1];
        v.z = acc[n * 4 + 2]; v.w = acc[n * 4 + 3];
        orow[n] = v;
    }
}

// ------------------------------------------------------------------ launcher
extern "C" void kernel_launch(void* const* d_in, const int* in_sizes, int n_in,
                              void* d_out, int out_size) {
    const float* x  = (const float*)d_in[0];
    const int*   ei = (const int*)d_in[1];     // int32 (JAX x64-disabled)
    const float* W1 = (const float*)d_in[2];
    const float* b1 = (const float*)d_in[3];
    const float* W2 = (const float*)d_in[4];
    const float* b2 = (const float*)d_in[5];
    const float* Wc = (const float*)d_in[6];
    const float* bc = (const float*)d_in[7];
    float*       out = (float*)d_out;

    const int Hdim = in_sizes[3];             // 64
    const int Fin  = in_sizes[2] / Hdim;      // 128
    const int N    = in_sizes[0] / Fin;       // 100000
    const int E    = in_sizes[1] / 2;         // 1000000
    (void)Hdim; (void)n_in; (void)out_size;

    const int TPB = 256;
    int nBlk  = (N + TPB - 1) / TPB;
    int eBlk  = (E + TPB - 1) / TPB;
    int gBlk  = (N + BM - 1) / BM;            // tiled gemm: 128 rows/block
    long long scatThreads = (long long)((E + 1) / 2) * 32;
    int scatBlk = (int)((scatThreads + TPB - 1) / TPB);

    // degrees -> dinv
    k_fill_deg<<<nBlk, TPB>>>(N);
    k_deg_accum<<<eBlk, TPB>>>(ei, E);
    k_dinv<<<nBlk, TPB>>>(N);

    // layer 1: A = x@W1 ; B1 = A*dinv^2 (fused) ; B1 += scatter(A)
    k_gemm<128, true, 1><<<gBlk, TPB>>>(x, W1, nullptr, N);
    k_scatter<1><<<scatBlk, TPB>>>(ei, E);

    // layer 2: A = relu(B1+b1)@W2 (fused load) ; B2 = A*dinv^2 ; B2 += scatter(A)
    k_gemm<64, false, 2><<<gBlk, TPB>>>(nullptr, W2, b1, N);
    k_scatter<2><<<scatBlk, TPB>>>(ei, E);

    // classifier (fuses relu(B2 + b2))
    k_final<<<nBlk, TPB>>>(b2, Wc, bc, out, N);
}

// round 7
// speedup vs baseline: 2.4884x; 1.3339x over previous
#include <cuda_runtime.h>
#include <cstdint>

#define NMAX 100000
#define EMAX 1000000
#define HF   64      // hidden features
#define CF   40      // classes

// Device-only scratch. Never passed from host.
__device__ __align__(16) float g_A [(size_t)NMAX * HF];  // A' = (in@W) * dinv[row]
__device__ __align__(16) float g_B [(size_t)NMAX * HF];  // aggregation output
__device__ __align__(16) float g_dinv[NMAX];
__device__ __align__(16) int   g_cnt[NMAX];              // in-degree counts
__device__ __align__(16) int   g_rowptr[NMAX + 1];       // CSR row pointers (by dst)
__device__ __align__(16) int   g_cur[NMAX];              // fill cursors
__device__ __align__(16) int   g_col[EMAX];              // CSR col = src, grouped by dst
__device__ __align__(16) int   g_bsum[1024];             // scan block sums
__device__ __align__(16) int   g_bsum2[1024];            // scanned block sums

// ------------------------------------------------------------- CSR build
__global__ void k_zero_cnt(int N) {
    int i = blockIdx.x * blockDim.x + threadIdx.x;
    if (i < N) g_cnt[i] = 0;
}
__global__ void k_count(const int* __restrict__ ei, int E) {
    int e = blockIdx.x * blockDim.x + threadIdx.x;
    if (e < E) atomicAdd(&g_cnt[ei[E + e]], 1);
}
// exclusive scan of g_cnt[0..N) into g_rowptr[0..N); 1024 items / block
__global__ void k_scanA(int n) {
    __shared__ int sm[256];
    int tid  = threadIdx.x;
    int idx  = blockIdx.x * 1024 + tid * 4;
    int v0 = 0, v1 = 0, v2 = 0, v3 = 0;
    if (idx + 3 < n) {
        int4 t = *reinterpret_cast<const int4*>(&g_cnt[idx]);
        v0 = t.x; v1 = t.y; v2 = t.z; v3 = t.w;
    } else {
        if (idx     < n) v0 = g_cnt[idx];
        if (idx + 1 < n) v1 = g_cnt[idx + 1];
        if (idx + 2 < n) v2 = g_cnt[idx + 2];
        if (idx + 3 < n) v3 = g_cnt[idx + 3];
    }
    sm[tid] = v0 + v1 + v2 + v3;
    __syncthreads();
    for (int off = 1; off < 256; off <<= 1) {
        int t = (tid >= off) ? sm[tid - off] : 0;
        __syncthreads();
        sm[tid] += t;
        __syncthreads();
    }
    int excl = (tid > 0) ? sm[tid - 1] : 0;
    if (tid == 255) g_bsum[blockIdx.x] = sm[255];
    if (idx     < n) g_rowptr[idx]     = excl;
    if (idx + 1 < n) g_rowptr[idx + 1] = excl + v0;
    if (idx + 2 < n) g_rowptr[idx + 2] = excl + v0 + v1;
    if (idx + 3 < n) g_rowptr[idx + 3] = excl + v0 + v1 + v2;
}
__global__ void k_scanB(int nb) {   // single block, 1024 threads
    __shared__ int sm[1024];
    int tid = threadIdx.x;
    sm[tid] = (tid < nb) ? g_bsum[tid] : 0;
    __syncthreads();
    for (int off = 1; off < 1024; off <<= 1) {
        int t = (tid >= off) ? sm[tid - off] : 0;
        __syncthreads();
        sm[tid] += t;
        __syncthreads();
    }
    g_bsum2[tid] = (tid > 0) ? sm[tid - 1] : 0;
}
__global__ void k_scanC(int n) {
    int i = blockIdx.x * blockDim.x + threadIdx.x;
    if (i < n) g_rowptr[i] += g_bsum2[i >> 10];
}
// cursors = rowptr copy; dinv from counts; rowptr[N] = E
__global__ void k_prep(int N, int E) {
    int i = blockIdx.x * blockDim.x + threadIdx.x;
    if (i < N) {
        g_cur[i]  = g_rowptr[i];
        g_dinv[i] = rsqrtf((float)(g_cnt[i] + 1));   // +1 self loop
    }
    if (i == 0) g_rowptr[N] = E;
}
__global__ void k_fill(const int* __restrict__ ei, int E) {
    int e = blockIdx.x * blockDim.x + threadIdx.x;
    if (e < E) {
        int s = ei[e];
        int d = ei[E + e];
        int pos = atomicAdd(&g_cur[d], 1);
        g_col[pos] = s;
    }
}

// ------------------------------------------------------- tiled GEMM (2D reg-blocked)
// g_A[row] = (in[row] @ W[K,64]) * dinv[row]     (A' form)
// in = X if SRC_EXT else relu(g_B + bias) applied during tile staging.
#define BM   128
#define BK   16
#define XSTR 132

template <int K, bool SRC_EXT>
__global__ void __launch_bounds__(256)
k_gemm(const float* __restrict__ X, const float* __restrict__ W,
       const float* __restrict__ bias, int N) {
    __shared__ float Ws[K * HF];
    __shared__ float Xs[BK * XSTR];
    __shared__ float bs[K];

    const int tid = threadIdx.x;
    {
        const float4* Wv = reinterpret_cast<const float4*>(W);
        float4* Wsv = reinterpret_cast<float4*>(Ws);
        for (int i = tid; i < K * HF / 4; i += 256) Wsv[i] = Wv[i];
        if (!SRC_EXT && tid < K) bs[tid] = bias[tid];
    }

    const int bm = blockIdx.x * BM;
    const int tc = tid & 15;
    const int tr = tid >> 4;

    const float* src = SRC_EXT ? X : (const float*)g_B;

    float acc[8][4];
#pragma unroll
    for (int i = 0; i < 8; i++)
#pragma unroll
        for (int j = 0; j < 4; j++) acc[i][j] = 0.0f;

    __syncthreads();

    for (int k0 = 0; k0 < K; k0 += BK) {
#pragma unroll
        for (int i = tid; i < BM * BK / 4; i += 256) {
            int row = i >> 2;
            int kq  = i & 3;
            int r   = bm + row;
            float4 v = make_float4(0.f, 0.f, 0.f, 0.f);
            if (r < N) {
                v = *reinterpret_cast<const float4*>(src + (size_t)r * K + k0 + kq * 4);
                if (!SRC_EXT) {
                    int kb = k0 + kq * 4;
                    v.x = fmaxf(v.x + bs[kb + 0], 0.0f);
                    v.y = fmaxf(v.y + bs[kb + 1], 0.0f);
                    v.z = fmaxf(v.z + bs[kb + 2], 0.0f);
                    v.w = fmaxf(v.w + bs[kb + 3], 0.0f);
                }
            }
            Xs[(kq * 4 + 0) * XSTR + row] = v.x;
            Xs[(kq * 4 + 1) * XSTR + row] = v.y;
            Xs[(kq * 4 + 2) * XSTR + row] = v.z;
            Xs[(kq * 4 + 3) * XSTR + row] = v.w;
        }
        __syncthreads();

#pragma unroll
        for (int kk = 0; kk < BK; kk++) {
            float4 xa = *reinterpret_cast<const float4*>(&Xs[kk * XSTR + tr * 8 + 0]);
            float4 xb = *reinterpret_cast<const float4*>(&Xs[kk * XSTR + tr * 8 + 4]);
            float4 wv = *reinterpret_cast<const float4*>(&Ws[(k0 + kk) * HF + tc * 4]);
            float xr[8] = {xa.x, xa.y, xa.z, xa.w, xb.x, xb.y, xb.z, xb.w};
#pragma unroll
            for (int i = 0; i < 8; i++) {
                acc[i][0] += xr[i] * wv.x;
                acc[i][1] += xr[i] * wv.y;
                acc[i][2] += xr[i] * wv.z;
                acc[i][3] += xr[i] * wv.w;
            }
        }
        __syncthreads();
    }

#pragma unroll
    for (int i = 0; i < 8; i++) {
        int r = bm + tr * 8 + i;
        if (r >= N) break;
        float di = g_dinv[r];
        float4 v = make_float4(acc[i][0] * di, acc[i][1] * di,
                               acc[i][2] * di, acc[i][3] * di);
        *reinterpret_cast<float4*>(g_A + (size_t)r * HF + tc * 4) = v;
    }
}

// ------------------------------------------------------------ CSR gather
// g_B[d,:] = dinv[d] * ( A'[d,:] + sum_{j in row d} A'[col[j],:] )
// Half-warp per dst row: 16 lanes x float4 = 64 floats.
__global__ void k_gather(int N) {
    int gt   = blockIdx.x * blockDim.x + threadIdx.x;
    int warp = gt >> 5;
    int lane = gt & 31;
    int d = warp * 2 + (lane >> 4);
    if (d >= N) return;
    int sub = lane & 15;

    const float4* Ap = reinterpret_cast<const float4*>(g_A);
    int beg = __ldg(&g_rowptr[d]);
    int end = __ldg(&g_rowptr[d + 1]);

    float4 acc = Ap[(size_t)d * 16 + sub];   // self loop term

    int j = beg;
    for (; j + 1 < end; j += 2) {
        int s0 = __ldg(&g_col[j]);
        int s1 = __ldg(&g_col[j + 1]);
        float4 v0 = Ap[(size_t)s0 * 16 + sub];
        float4 v1 = Ap[(size_t)s1 * 16 + sub];
        acc.x += v0.x + v1.x;
        acc.y += v0.y + v1.y;
        acc.z += v0.z + v1.z;
        acc.w += v0.w + v1.w;
    }
    if (j < end) {
        int s = __ldg(&g_col[j]);
        float4 v = Ap[(size_t)s * 16 + sub];
        acc.x += v.x; acc.y += v.y; acc.z += v.z; acc.w += v.w;
    }

    float di = g_dinv[d];
    acc.x *= di; acc.y *= di; acc.z *= di; acc.w *= di;
    reinterpret_cast<float4*>(g_B)[(size_t)d * 16 + sub] = acc;
}

// ------------------------------------------- classifier: out = relu(B + b2) @ Wc + bc
__global__ void __launch_bounds__(256)
k_final(const float* __restrict__ b2, const float* __restrict__ Wc,
        const float* __restrict__ bc, float* __restrict__ out, int N) {
    __shared__ float Ws[HF * CF];
    __shared__ float bs[HF];
    __shared__ float bcs[CF];
    for (int i = threadIdx.x; i < HF * CF; i += blockDim.x) Ws[i] = Wc[i];
    if (threadIdx.x < HF) bs[threadIdx.x] = b2[threadIdx.x];
    if (threadIdx.x < CF) bcs[threadIdx.x] = bc[threadIdx.x];
    __syncthreads();

    int row = blockIdx.x * blockDim.x + threadIdx.x;
    if (row >= N) return;

    float acc[CF];
#pragma unroll
    for (int n = 0; n < CF; n++) acc[n] = bcs[n];

    const float4* br = reinterpret_cast<const float4*>(g_B + (size_t)row * HF);
#pragma unroll
    for (int k4 = 0; k4 < HF / 4; k4++) {
        float4 v = br[k4];
        int k = k4 * 4;
        float a0 = fmaxf(v.x + bs[k + 0], 0.0f);
        float a1 = fmaxf(v.y + bs[k + 1], 0.0f);
        float a2 = fmaxf(v.z + bs[k + 2], 0.0f);
        float a3 = fmaxf(v.w + bs[k + 3], 0.0f);
#pragma unroll
        for (int n = 0; n < CF; n++) {
            acc[n] += a0 * Ws[(k + 0) * CF + n];
            acc[n] += a1 * Ws[(k + 1) * CF + n];
            acc[n] += a2 * Ws[(k + 2) * CF + n];
            acc[n] += a3 * Ws[(k + 3) * CF + n];
        }
    }

    float4* orow = reinterpret_cast<float4*>(out + (size_t)row * CF);
#pragma unroll
    for (int n = 0; n < CF / 4; n++) {
        float4 v;
        v.x = acc[n * 4 + 0]; v.y = acc[n * 4 + 1];
        v.z = acc[n * 4 + 2]; v.w = acc[n * 4 + 3];
        orow[n] = v;
    }
}

// ------------------------------------------------------------------ launcher
extern "C" void kernel_launch(void* const* d_in, const int* in_sizes, int n_in,
                              void* d_out, int out_size) {
    const float* x  = (const float*)d_in[0];
    const int*   ei = (const int*)d_in[1];     // int32 (JAX x64-disabled)
    const float* W1 = (const float*)d_in[2];
    const float* b1 = (const float*)d_in[3];
    const float* W2 = (const float*)d_in[4];
    const float* b2 = (const float*)d_in[5];
    const float* Wc = (const float*)d_in[6];
    const float* bc = (const float*)d_in[7];
    float*       out = (float*)d_out;

    const int Hdim = in_sizes[3];             // 64
    const int Fin  = in_sizes[2] / Hdim;      // 128
    const int N    = in_sizes[0] / Fin;       // 100000
    const int E    = in_sizes[1] / 2;         // 1000000
    (void)Hdim; (void)n_in; (void)out_size;

    const int TPB = 256;
    int nBlk  = (N + TPB - 1) / TPB;
    int eBlk  = (E + TPB - 1) / TPB;
    int gBlk  = (N + BM - 1) / BM;
    int sBlkA = (N + 1023) / 1024;            // scan blocks (98)
    long long gatThreads = (long long)((N + 1) / 2) * 32;
    int gatBlk = (int)((gatThreads + TPB - 1) / TPB);

    // CSR build (also produces dinv)
    k_zero_cnt<<<nBlk, TPB>>>(N);
    k_count<<<eBlk, TPB>>>(ei, E);
    k_scanA<<<sBlkA, 256>>>(N);
    k_scanB<<<1, 1024>>>(sBlkA);
    k_scanC<<<nBlk, TPB>>>(N);
    k_prep<<<nBlk, TPB>>>(N, E);
    k_fill<<<eBlk, TPB>>>(ei, E);

    // layer 1: A' = (x@W1)*dinv ; B = gather(A')
    k_gemm<128, true><<<gBlk, TPB>>>(x, W1, nullptr, N);
    k_gather<<<gatBlk, TPB>>>(N);

    // layer 2: A' = (relu(B+b1)@W2)*dinv ; B = gather(A')
    k_gemm<64, false><<<gBlk, TPB>>>(nullptr, W2, b1, N);
    k_gather<<<gatBlk, TPB>>>(N);

    // classifier (fuses relu(B + b2))
    k_final<<<nBlk, TPB>>>(b2, Wc, bc, out, N);
}

// round 8
// speedup vs baseline: 2.4906x; 1.0009x over previous
#include <cuda_runtime.h>
#include <cstdint>

#define NMAX 100000
#define EMAX 1000000
#define HF   64      // hidden features
#define CF   40      // classes
#define CFP  48      // padded classifier cols (48 = 12 groups of 4)

// Device-only scratch. Never passed from host.
__device__ __align__(16) float g_A [(size_t)NMAX * HF];  // A' = (in@W) * dinv[row]
__device__ __align__(16) float g_B [(size_t)NMAX * HF];  // aggregation output
__device__ __align__(16) float g_dinv[NMAX];
__device__ __align__(16) int   g_cnt[NMAX];              // in-degree counts
__device__ __align__(16) int   g_rowptr[NMAX + 1];       // CSR row pointers (by dst)
__device__ __align__(16) int   g_cur[NMAX];              // fill cursors
__device__ __align__(16) int   g_col[EMAX];              // CSR col = src, grouped by dst
__device__ __align__(16) int   g_bsum[1024];             // scan block sums
__device__ __align__(16) int   g_bsum2[1024];            // scanned block sums

// ------------------------------------------------------------- CSR build
__global__ void k_zero_cnt(int N) {
    int i = blockIdx.x * blockDim.x + threadIdx.x;
    if (i < N) g_cnt[i] = 0;
}
__global__ void k_count(const int* __restrict__ ei, int E) {
    int e = blockIdx.x * blockDim.x + threadIdx.x;
    if (e < E) atomicAdd(&g_cnt[ei[E + e]], 1);
}
// exclusive scan of g_cnt[0..N) into g_rowptr[0..N); 1024 items / block
__global__ void k_scanA(int n) {
    __shared__ int sm[256];
    int tid  = threadIdx.x;
    int idx  = blockIdx.x * 1024 + tid * 4;
    int v0 = 0, v1 = 0, v2 = 0, v3 = 0;
    if (idx + 3 < n) {
        int4 t = *reinterpret_cast<const int4*>(&g_cnt[idx]);
        v0 = t.x; v1 = t.y; v2 = t.z; v3 = t.w;
    } else {
        if (idx     < n) v0 = g_cnt[idx];
        if (idx + 1 < n) v1 = g_cnt[idx + 1];
        if (idx + 2 < n) v2 = g_cnt[idx + 2];
        if (idx + 3 < n) v3 = g_cnt[idx + 3];
    }
    sm[tid] = v0 + v1 + v2 + v3;
    __syncthreads();
    for (int off = 1; off < 256; off <<= 1) {
        int t = (tid >= off) ? sm[tid - off] : 0;
        __syncthreads();
        sm[tid] += t;
        __syncthreads();
    }
    int excl = (tid > 0) ? sm[tid - 1] : 0;
    if (tid == 255) g_bsum[blockIdx.x] = sm[255];
    if (idx     < n) g_rowptr[idx]     = excl;
    if (idx + 1 < n) g_rowptr[idx + 1] = excl + v0;
    if (idx + 2 < n) g_rowptr[idx + 2] = excl + v0 + v1;
    if (idx + 3 < n) g_rowptr[idx + 3] = excl + v0 + v1 + v2;
}
// warp-shuffle scan of block sums (nb <= 128): 128 threads, 4 warps
__global__ void k_scanB(int nb) {
    __shared__ int wsum[4];
    int tid  = threadIdx.x;
    int lane = tid & 31;
    int wid  = tid >> 5;
    int v = (tid < nb) ? g_bsum[tid] : 0;
    int inc = v;
#pragma unroll
    for (int off = 1; off < 32; off <<= 1) {
        int t = __shfl_up_sync(0xFFFFFFFF, inc, off);
        if (lane >= off) inc += t;
    }
    if (lane == 31) wsum[wid] = inc;
    __syncthreads();
    if (wid == 0 && lane < 4) {
        int s = wsum[lane];
        int si = s;
#pragma unroll
        for (int off = 1; off < 4; off <<= 1) {
            int t = __shfl_up_sync(0xF, si, off);
            if (lane >= off) si += t;
        }
        wsum[lane] = si - s;   // exclusive warp offsets
    }
    __syncthreads();
    g_bsum2[tid] = inc - v + wsum[wid];   // exclusive scan result
}
// add block offsets + cursors + dinv + rowptr[N] in ONE pass
__global__ void k_scanC_prep(int N, int E) {
    int i = blockIdx.x * blockDim.x + threadIdx.x;
    if (i < N) {
        int rp = g_rowptr[i] + g_bsum2[i >> 10];
        g_rowptr[i] = rp;
        g_cur[i]    = rp;
        g_dinv[i]   = rsqrtf((float)(g_cnt[i] + 1));   // +1 self loop
    }
    if (i == 0) g_rowptr[N] = E;
}
__global__ void k_fill(const int* __restrict__ ei, int E) {
    int e = blockIdx.x * blockDim.x + threadIdx.x;
    if (e < E) {
        int s = ei[e];
        int d = ei[E + e];
        int pos = atomicAdd(&g_cur[d], 1);
        g_col[pos] = s;
    }
}

// ------------------------------------------------------- tiled GEMM (2D reg-blocked)
// g_A[row] = (in[row] @ W[K,64]) * dinv[row]     (A' form)
// in = X if SRC_EXT else relu(g_B + bias) applied during tile staging.
#define BM   128
#define BK   16
#define XSTR 132

template <int K, bool SRC_EXT>
__global__ void __launch_bounds__(256)
k_gemm(const float* __restrict__ X, const float* __restrict__ W,
       const float* __restrict__ bias, int N) {
    __shared__ float Ws[K * HF];
    __shared__ float Xs[BK * XSTR];
    __shared__ float bs[K];

    const int tid = threadIdx.x;
    {
        const float4* Wv = reinterpret_cast<const float4*>(W);
        float4* Wsv = reinterpret_cast<float4*>(Ws);
        for (int i = tid; i < K * HF / 4; i += 256) Wsv[i] = Wv[i];
        if (!SRC_EXT && tid < K) bs[tid] = bias[tid];
    }

    const int bm = blockIdx.x * BM;
    const int tc = tid & 15;
    const int tr = tid >> 4;

    const float* src = SRC_EXT ? X : (const float*)g_B;

    float acc[8][4];
#pragma unroll
    for (int i = 0; i < 8; i++)
#pragma unroll
        for (int j = 0; j < 4; j++) acc[i][j] = 0.0f;

    __syncthreads();

    for (int k0 = 0; k0 < K; k0 += BK) {
#pragma unroll
        for (int i = tid; i < BM * BK / 4; i += 256) {
            int row = i >> 2;
            int kq  = i & 3;
            int r   = bm + row;
            float4 v = make_float4(0.f, 0.f, 0.f, 0.f);
            if (r < N) {
                v = *reinterpret_cast<const float4*>(src + (size_t)r * K + k0 + kq * 4);
                if (!SRC_EXT) {
                    int kb = k0 + kq * 4;
                    v.x = fmaxf(v.x + bs[kb + 0], 0.0f);
                    v.y = fmaxf(v.y + bs[kb + 1], 0.0f);
                    v.z = fmaxf(v.z + bs[kb + 2], 0.0f);
                    v.w = fmaxf(v.w + bs[kb + 3], 0.0f);
                }
            }
            Xs[(kq * 4 + 0) * XSTR + row] = v.x;
            Xs[(kq * 4 + 1) * XSTR + row] = v.y;
            Xs[(kq * 4 + 2) * XSTR + row] = v.z;
            Xs[(kq * 4 + 3) * XSTR + row] = v.w;
        }
        __syncthreads();

#pragma unroll
        for (int kk = 0; kk < BK; kk++) {
            float4 xa = *reinterpret_cast<const float4*>(&Xs[kk * XSTR + tr * 8 + 0]);
            float4 xb = *reinterpret_cast<const float4*>(&Xs[kk * XSTR + tr * 8 + 4]);
            float4 wv = *reinterpret_cast<const float4*>(&Ws[(k0 + kk) * HF + tc * 4]);
            float xr[8] = {xa.x, xa.y, xa.z, xa.w, xb.x, xb.y, xb.z, xb.w};
#pragma unroll
            for (int i = 0; i < 8; i++) {
                acc[i][0] += xr[i] * wv.x;
                acc[i][1] += xr[i] * wv.y;
                acc[i][2] += xr[i] * wv.z;
                acc[i][3] += xr[i] * wv.w;
            }
        }
        __syncthreads();
    }

#pragma unroll
    for (int i = 0; i < 8; i++) {
        int r = bm + tr * 8 + i;
        if (r >= N) break;
        float di = g_dinv[r];
        float4 v = make_float4(acc[i][0] * di, acc[i][1] * di,
                               acc[i][2] * di, acc[i][3] * di);
        *reinterpret_cast<float4*>(g_A + (size_t)r * HF + tc * 4) = v;
    }
}

// ------------------------------------------------------------ CSR gather
// g_B[d,:] = dinv[d] * ( A'[d,:] + sum_{j in row d} A'[col[j],:] )
// Half-warp per dst row: 16 lanes x float4 = 64 floats.
__global__ void k_gather(int N) {
    int gt   = blockIdx.x * blockDim.x + threadIdx.x;
    int warp = gt >> 5;
    int lane = gt & 31;
    int d = warp * 2 + (lane >> 4);
    if (d >= N) return;
    int sub = lane & 15;

    const float4* Ap = reinterpret_cast<const float4*>(g_A);
    int beg = __ldg(&g_rowptr[d]);
    int end = __ldg(&g_rowptr[d + 1]);

    float4 acc = Ap[(size_t)d * 16 + sub];   // self loop term

    int j = beg;
    for (; j + 1 < end; j += 2) {
        int s0 = __ldg(&g_col[j]);
        int s1 = __ldg(&g_col[j + 1]);
        float4 v0 = Ap[(size_t)s0 * 16 + sub];
        float4 v1 = Ap[(size_t)s1 * 16 + sub];
        acc.x += v0.x + v1.x;
        acc.y += v0.y + v1.y;
        acc.z += v0.z + v1.z;
        acc.w += v0.w + v1.w;
    }
    if (j < end) {
        int s = __ldg(&g_col[j]);
        float4 v = Ap[(size_t)s * 16 + sub];
        acc.x += v.x; acc.y += v.y; acc.z += v.z; acc.w += v.w;
    }

    float di = g_dinv[d];
    acc.x *= di; acc.y *= di; acc.z *= di; acc.w *= di;
    reinterpret_cast<float4*>(g_B)[(size_t)d * 16 + sub] = acc;
}

// ---------------------------------- tiled classifier: out = relu(B + b2) @ Wc + bc
// 2D reg-blocked like k_gemm: 128 rows x 48 cols (Wc zero-padded 40->48),
// 192 threads = 16 row-groups x 12 col-groups, 8x4 register tile.
__global__ void __launch_bounds__(192)
k_final(const float* __restrict__ b2, const float* __restrict__ Wc,
        const float* __restrict__ bc, float* __restrict__ out, int N) {
    __shared__ float Ws[HF * CFP];     // 64 x 48, zero-padded
    __shared__ float Xs[BK * XSTR];
    __shared__ float bs[HF];
    __shared__ float bcs[CFP];

    const int tid = threadIdx.x;
    for (int i = tid; i < HF * CFP; i += 192) {
        int k = i / CFP, c = i % CFP;
        Ws[i] = (c < CF) ? Wc[k * CF + c] : 0.0f;
    }
    if (tid < HF)  bs[tid]  = b2[tid];
    if (tid < CFP) bcs[tid] = (tid < CF) ? bc[tid] : 0.0f;

    const int bm = blockIdx.x * BM;
    const int tc = tid % 12;           // col group: cols tc*4 .. tc*4+3 (of 48)
    const int tr = tid / 12;           // row group: rows tr*8 .. tr*8+7

    float acc[8][4];
#pragma unroll
    for (int i = 0; i < 8; i++)
#pragma unroll
        for (int j = 0; j < 4; j++) acc[i][j] = 0.0f;

    __syncthreads();

    for (int k0 = 0; k0 < HF; k0 += BK) {
        for (int i = tid; i < BM * BK / 4; i += 192) {
            int row = i >> 2;
            int kq  = i & 3;
            int r   = bm + row;
            float4 v = make_float4(0.f, 0.f, 0.f, 0.f);
            if (r < N) {
                v = *reinterpret_cast<const float4*>(g_B + (size_t)r * HF + k0 + kq * 4);
                int kb = k0 + kq * 4;
                v.x = fmaxf(v.x + bs[kb + 0], 0.0f);
                v.y = fmaxf(v.y + bs[kb + 1], 0.0f);
                v.z = fmaxf(v.z + bs[kb + 2], 0.0f);
                v.w = fmaxf(v.w + bs[kb + 3], 0.0f);
            }
            Xs[(kq * 4 + 0) * XSTR + row] = v.x;
            Xs[(kq * 4 + 1) * XSTR + row] = v.y;
            Xs[(kq * 4 + 2) * XSTR + row] = v.z;
            Xs[(kq * 4 + 3) * XSTR + row] = v.w;
        }
        __syncthreads();

#pragma unroll
        for (int kk = 0; kk < BK; kk++) {
            float4 xa = *reinterpret_cast<const float4*>(&Xs[kk * XSTR + tr * 8 + 0]);
            float4 xb = *reinterpret_cast<const float4*>(&Xs[kk * XSTR + tr * 8 + 4]);
            float4 wv = *reinterpret_cast<const float4*>(&Ws[(k0 + kk) * CFP + tc * 4]);
            float xr[8] = {xa.x, xa.y, xa.z, xa.w, xb.x, xb.y, xb.z, xb.w};
#pragma unroll
            for (int i = 0; i < 8; i++) {
                acc[i][0] += xr[i] * wv.x;
                acc[i][1] += xr[i] * wv.y;
                acc[i][2] += xr[i] * wv.z;
                acc[i][3] += xr[i] * wv.w;
            }
        }
        __syncthreads();
    }

    if (tc * 4 < CF) {   // only real output columns
#pragma unroll
        for (int i = 0; i < 8; i++) {
            int r = bm + tr * 8 + i;
            if (r >= N) break;
            float4 v = make_float4(acc[i][0] + bcs[tc * 4 + 0],
                                   acc[i][1] + bcs[tc * 4 + 1],
                                   acc[i][2] + bcs[tc * 4 + 2],
                                   acc[i][3] + bcs[tc * 4 + 3]);
            *reinterpret_cast<float4*>(out + (size_t)r * CF + tc * 4) = v;
        }
    }
}

// ------------------------------------------------------------------ launcher
extern "C" void kernel_launch(void* const* d_in, const int* in_sizes, int n_in,
                              void* d_out, int out_size) {
    const float* x  = (const float*)d_in[0];
    const int*   ei = (const int*)d_in[1];     // int32 (JAX x64-disabled)
    const float* W1 = (const float*)d_in[2];
    const float* b1 = (const float*)d_in[3];
    const float* W2 = (const float*)d_in[4];
    const float* b2 = (const float*)d_in[5];
    const float* Wc = (const float*)d_in[6];
    const float* bc = (const float*)d_in[7];
    float*       out = (float*)d_out;

    const int Hdim = in_sizes[3];             // 64
    const int Fin  = in_sizes[2] / Hdim;      // 128
    const int N    = in_sizes[0] / Fin;       // 100000
    const int E    = in_sizes[1] / 2;         // 1000000
    (void)Hdim; (void)n_in; (void)out_size;

    const int TPB = 256;
    int nBlk  = (N + TPB - 1) / TPB;
    int eBlk  = (E + TPB - 1) / TPB;
    int gBlk  = (N + BM - 1) / BM;
    int sBlkA = (N + 1023) / 1024;            // scan blocks (98)
    long long gatThreads = (long long)((N + 1) / 2) * 32;
    int gatBlk = (int)((gatThreads + TPB - 1) / TPB);

    // CSR build (also produces dinv)
    k_zero_cnt<<<nBlk, TPB>>>(N);
    k_count<<<eBlk, TPB>>>(ei, E);
    k_scanA<<<sBlkA, 256>>>(N);
    k_scanB<<<1, 128>>>(sBlkA);
    k_scanC_prep<<<nBlk, TPB>>>(N, E);
    k_fill<<<eBlk, TPB>>>(ei, E);

    // layer 1: A' = (x@W1)*dinv ; B = gather(A')
    k_gemm<128, true><<<gBlk, TPB>>>(x, W1, nullptr, N);
    k_gather<<<gatBlk, TPB>>>(N);

    // layer 2: A' = (relu(B+b1)@W2)*dinv ; B = gather(A')
    k_gemm<64, false><<<gBlk, TPB>>>(nullptr, W2, b1, N);
    k_gather<<<gatBlk, TPB>>>(N);

    // classifier (tiled, fuses relu(B + b2))
    k_final<<<gBlk, 192>>>(b2, Wc, bc, out, N);
}